// round 1
// baseline (speedup 1.0000x reference)
#include <cuda_runtime.h>

// Problem constants
#define Bq   8
#define Sq   2048
#define Dq   1024
#define Hq   16
#define DHq  64
#define Mrows (Bq*Sq)      // 16384
#define BHn   (Bq*Hq)      // 128
#define OUT_MAIN (Mrows*Dq)  // 16777216 floats of `outputs`

__device__ float g_Tq[Mrows*32];
__device__ float g_Tk[Mrows*32];
__device__ float g_Q [Mrows*Dq];
__device__ float g_K [Mrows*Dq];
__device__ float g_V [Mrows*Dq];
__device__ float g_VV[BHn*DHq*DHq];     // [bh][d][f]
__device__ float g_VVV[Mrows*Dq];       // [b][h][s][f] flattened (== flat reshape layout)
__device__ float g_O1[Mrows*Dq];
__device__ float g_O2[Mrows*Dq];

// ---------------------------------------------------------------------------
// proj1: T = X @ W1   (X: [16384,1024], W1: [1024,32])
// block: (32,8), grid: 2048.  8 rows per block staged in smem.
// ---------------------------------------------------------------------------
__global__ void k_proj1(const float* __restrict__ X, const float* __restrict__ W, int sel) {
    __shared__ float As[8][1024];
    float* T = sel ? g_Tk : g_Tq;
    int tx = threadIdx.x, ty = threadIdx.y;
    int t = ty * 32 + tx;
    int row0 = blockIdx.x * 8;
    #pragma unroll
    for (int i = 0; i < 32; i++) {
        int idx = t + i * 256;
        As[idx >> 10][idx & 1023] = X[(size_t)(row0 + (idx >> 10)) * 1024 + (idx & 1023)];
    }
    __syncthreads();
    float sum = 0.f;
    #pragma unroll 8
    for (int k = 0; k < 1024; k++) sum += As[ty][k] * W[k * 32 + tx];
    T[(size_t)(row0 + ty) * 32 + tx] = sum;
}

// ---------------------------------------------------------------------------
// proj2: O = T @ W2   (T: [16384,32], W2: [32,1024])
// block: 256, 16 rows per block, each thread 4 output columns.
// ---------------------------------------------------------------------------
__global__ void k_proj2(const float* __restrict__ W2, int sel) {
    __shared__ float ts[16][32];
    const float* T = sel ? g_Tk : g_Tq;
    float* O = sel ? g_K : g_Q;
    int t = threadIdx.x;
    int row0 = blockIdx.x * 16;
    for (int i = t; i < 512; i += 256) ts[i >> 5][i & 31] = T[(size_t)row0 * 32 + i];
    __syncthreads();
    float acc[16][4];
    #pragma unroll
    for (int r = 0; r < 16; r++)
        #pragma unroll
        for (int j = 0; j < 4; j++) acc[r][j] = 0.f;
    for (int k = 0; k < 32; k++) {
        float wv[4];
        #pragma unroll
        for (int j = 0; j < 4; j++) wv[j] = W2[k * 1024 + t + j * 256];
        #pragma unroll
        for (int r = 0; r < 16; r++) {
            float tv = ts[r][k];
            #pragma unroll
            for (int j = 0; j < 4; j++) acc[r][j] += tv * wv[j];
        }
    }
    #pragma unroll
    for (int r = 0; r < 16; r++)
        #pragma unroll
        for (int j = 0; j < 4; j++)
            O[(size_t)(row0 + r) * 1024 + t + j * 256] = acc[r][j];
}

// ---------------------------------------------------------------------------
// sgemm: C[16384,1024] = A[16384,1024] @ Bw[1024,1024]
// classic 128x128x8 tile, 8x8 per thread, 256 threads.
// sel=0: A=Aext (input_V), C=g_V.  sel=1: A=g_O1, C=g_O2.
// ---------------------------------------------------------------------------
__global__ void k_sgemm(const float* __restrict__ Aext, const float* __restrict__ Bw, int sel) {
    const int K = 1024, N = 1024;
    const float* A = sel ? g_O1 : Aext;
    float* C = sel ? g_O2 : g_V;
    __shared__ float As[8][128];
    __shared__ float Bs[8][128];
    int tid = threadIdx.x;
    int aRow = tid >> 1, aCol = (tid & 1) * 4;
    int bRow = tid >> 5, bCol = (tid & 31) * 4;
    int tRow = (tid >> 4) * 8, tCol = (tid & 15) * 8;
    const float* Ab = A + (size_t)blockIdx.y * 128 * K;
    const float* Bb = Bw + blockIdx.x * 128;
    float acc[8][8];
    #pragma unroll
    for (int i = 0; i < 8; i++)
        #pragma unroll
        for (int j = 0; j < 8; j++) acc[i][j] = 0.f;
    for (int k0 = 0; k0 < K; k0 += 8) {
        float4 a4 = *(const float4*)(Ab + (size_t)aRow * K + k0 + aCol);
        As[aCol + 0][aRow] = a4.x; As[aCol + 1][aRow] = a4.y;
        As[aCol + 2][aRow] = a4.z; As[aCol + 3][aRow] = a4.w;
        *(float4*)&Bs[bRow][bCol] = *(const float4*)(Bb + (size_t)(k0 + bRow) * N + bCol);
        __syncthreads();
        #pragma unroll
        for (int kk = 0; kk < 8; kk++) {
            float4 a0 = *(const float4*)&As[kk][tRow];
            float4 a1 = *(const float4*)&As[kk][tRow + 4];
            float4 b0 = *(const float4*)&Bs[kk][tCol];
            float4 b1 = *(const float4*)&Bs[kk][tCol + 4];
            float ar[8] = {a0.x, a0.y, a0.z, a0.w, a1.x, a1.y, a1.z, a1.w};
            float br[8] = {b0.x, b0.y, b0.z, b0.w, b1.x, b1.y, b1.z, b1.w};
            #pragma unroll
            for (int i = 0; i < 8; i++)
                #pragma unroll
                for (int j = 0; j < 8; j++) acc[i][j] += ar[i] * br[j];
        }
        __syncthreads();
    }
    float* Cb = C + (size_t)blockIdx.y * 128 * N + blockIdx.x * 128;
    #pragma unroll
    for (int i = 0; i < 8; i++)
        #pragma unroll
        for (int j = 0; j < 8; j += 4)
            *(float4*)(Cb + (size_t)(tRow + i) * N + tCol + j) =
                make_float4(acc[i][j], acc[i][j+1], acc[i][j+2], acc[i][j+3]);
}

// ---------------------------------------------------------------------------
// scores: attn[b,h,d,s] = scale * sum_f A[f,d] * K[b,h,s,f]   (raw scores)
// grid: (S/64, BH), block 256. 64 s-values per block, each thread 16 d.
// ---------------------------------------------------------------------------
__global__ void k_scores(const float* __restrict__ Amat, float* __restrict__ attn) {
    __shared__ float Asm[64][64];    // Asm[f][d]
    __shared__ float Ksm[64][65];    // Ksm[sl][f]
    int bh = blockIdx.y;
    int b = bh >> 4, h = bh & 15;
    int s0 = blockIdx.x * 64;
    int t = threadIdx.x;
    for (int i = t; i < 4096; i += 256) Asm[i >> 6][i & 63] = Amat[i];
    for (int i = t; i < 4096; i += 256) {
        int sl = i >> 6, f = i & 63;
        Ksm[sl][f] = g_K[(size_t)(b * Sq + s0 + sl) * 1024 + h * 64 + f];
    }
    __syncthreads();
    int sl = t & 63, dg = t >> 6;           // dg in [0,4)
    float acc[16];
    #pragma unroll
    for (int i = 0; i < 16; i++) acc[i] = 0.f;
    #pragma unroll 4
    for (int fb = 0; fb < 64; fb += 16) {
        float kr[16];
        #pragma unroll
        for (int q = 0; q < 16; q++) kr[q] = Ksm[sl][fb + q];
        #pragma unroll
        for (int dd = 0; dd < 16; dd++) {
            int d = dg * 16 + dd;
            float s = 0.f;
            #pragma unroll
            for (int q = 0; q < 16; q++) s += Asm[fb + q][d] * kr[q];
            acc[dd] += s;
        }
    }
    #pragma unroll
    for (int dd = 0; dd < 16; dd++) {
        int d = dg * 16 + dd;
        attn[((size_t)(bh * 64 + d)) * Sq + s0 + sl] = acc[dd] * 0.125f;
    }
}

// ---------------------------------------------------------------------------
// softmax over s (row length 2048), in place. grid: BH*64, block 256.
// ---------------------------------------------------------------------------
__global__ void k_softmax(float* __restrict__ attn) {
    __shared__ float smx[8];
    __shared__ float sms[8];
    float* p = attn + (size_t)blockIdx.x * Sq;
    int t = threadIdx.x;
    float v[8];
    float m = -1e30f;
    #pragma unroll
    for (int i = 0; i < 8; i++) { v[i] = p[t + i * 256]; m = fmaxf(m, v[i]); }
    #pragma unroll
    for (int o = 16; o > 0; o >>= 1) m = fmaxf(m, __shfl_xor_sync(0xffffffffu, m, o));
    if ((t & 31) == 0) smx[t >> 5] = m;
    __syncthreads();
    m = smx[0];
    #pragma unroll
    for (int i = 1; i < 8; i++) m = fmaxf(m, smx[i]);
    float l = 0.f;
    #pragma unroll
    for (int i = 0; i < 8; i++) { v[i] = __expf(v[i] - m); l += v[i]; }
    #pragma unroll
    for (int o = 16; o > 0; o >>= 1) l += __shfl_xor_sync(0xffffffffu, l, o);
    if ((t & 31) == 0) sms[t >> 5] = l;
    __syncthreads();
    l = 0.f;
    #pragma unroll
    for (int i = 0; i < 8; i++) l += sms[i];
    float inv = 1.f / l;
    #pragma unroll
    for (int i = 0; i < 8; i++) p[t + i * 256] = v[i] * inv;
}

// ---------------------------------------------------------------------------
// VV[bh][d][f] = sum_s attn[bh,d,s] * V[b,s,h*64+f]   ([64,2048]@[2048,64])
// grid: BH, block 256 (16x16 thread tiles of 4x4).
// ---------------------------------------------------------------------------
__global__ void k_vv(const float* __restrict__ attn) {
    __shared__ float At[64][65];
    __shared__ float Vs[64][65];
    int bh = blockIdx.x;
    int b = bh >> 4, h = bh & 15;
    int t = threadIdx.x;
    int tr = t >> 4, tc = t & 15;
    float acc[4][4];
    #pragma unroll
    for (int i = 0; i < 4; i++)
        #pragma unroll
        for (int j = 0; j < 4; j++) acc[i][j] = 0.f;
    for (int sc0 = 0; sc0 < Sq; sc0 += 64) {
        for (int i = t; i < 4096; i += 256) {
            int d = i >> 6, ss = i & 63;
            At[d][ss] = attn[((size_t)(bh * 64 + d)) * Sq + sc0 + ss];
        }
        for (int i = t; i < 4096; i += 256) {
            int ss = i >> 6, f = i & 63;
            Vs[ss][f] = g_V[(size_t)(b * Sq + sc0 + ss) * 1024 + h * 64 + f];
        }
        __syncthreads();
        #pragma unroll 8
        for (int ss = 0; ss < 64; ss++) {
            float av[4], bv[4];
            #pragma unroll
            for (int i = 0; i < 4; i++) av[i] = At[tr * 4 + i][ss];
            #pragma unroll
            for (int j = 0; j < 4; j++) bv[j] = Vs[ss][tc * 4 + j];
            #pragma unroll
            for (int i = 0; i < 4; i++)
                #pragma unroll
                for (int j = 0; j < 4; j++) acc[i][j] += av[i] * bv[j];
        }
        __syncthreads();
    }
    #pragma unroll
    for (int i = 0; i < 4; i++)
        #pragma unroll
        for (int j = 0; j < 4; j++)
            g_VV[(size_t)bh * 4096 + (tr * 4 + i) * 64 + tc * 4 + j] = acc[i][j];
}

// ---------------------------------------------------------------------------
// stage 2 fused: scores2 = Q@A^T * scale; softmax over d (64); VVV = p @ VV
// Online-softmax per thread (one s per thread). grid: (S/128, BH), block 128.
// ---------------------------------------------------------------------------
__global__ void k_stage2(const float* __restrict__ Amat) {
    __shared__ float Asm[64][64];   // A[d][f]
    __shared__ float VVs[64][64];   // VV[d][f]
    int bh = blockIdx.y;
    int b = bh >> 4, h = bh & 15;
    int s0 = blockIdx.x * 128;
    int t = threadIdx.x;
    for (int i = t; i < 4096; i += 128) Asm[i >> 6][i & 63] = Amat[i];
    for (int i = t; i < 4096; i += 128) VVs[i >> 6][i & 63] = g_VV[(size_t)bh * 4096 + i];
    __syncthreads();
    int s = s0 + t;
    const float* Qrow = g_Q + (size_t)(b * Sq + s) * 1024 + h * 64;
    float qr[64];
    #pragma unroll
    for (int f4 = 0; f4 < 64; f4 += 4) {
        float4 q = *(const float4*)(Qrow + f4);
        qr[f4] = q.x; qr[f4 + 1] = q.y; qr[f4 + 2] = q.z; qr[f4 + 3] = q.w;
    }
    float out[64];
    #pragma unroll
    for (int f = 0; f < 64; f++) out[f] = 0.f;
    float m = -1e30f, l = 0.f;
    for (int d = 0; d < 64; d++) {
        float sc = 0.f;
        #pragma unroll
        for (int f = 0; f < 64; f++) sc += qr[f] * Asm[d][f];
        sc *= 0.125f;
        float mn = fmaxf(m, sc);
        float fac = __expf(m - mn);
        float pp = __expf(sc - mn);
        l = l * fac + pp;
        #pragma unroll
        for (int f = 0; f < 64; f++) out[f] = out[f] * fac + pp * VVs[d][f];
        m = mn;
    }
    float inv = 1.f / l;
    float* Orow = g_VVV + ((size_t)bh * Sq + s) * 64;
    #pragma unroll
    for (int f = 0; f < 64; f += 4)
        *(float4*)(Orow + f) = make_float4(out[f] * inv, out[f+1] * inv,
                                           out[f+2] * inv, out[f+3] * inv);
}

// ---------------------------------------------------------------------------
// LayerNorm over last dim (1024), x = in1 + res.
// sel=0: in1=g_VVV, res=rese(input_Q), out=g_O1
// sel=1: in1=g_O2,  res=g_O1,          out=oute(d_out)
// grid: 16384, block 256.
// ---------------------------------------------------------------------------
__global__ void k_ln(const float* __restrict__ rese, const float* __restrict__ g,
                     const float* __restrict__ bb, float* __restrict__ oute, int sel) {
    const float* in1 = sel ? g_O2 : g_VVV;
    const float* res = sel ? g_O1 : rese;
    float* out = sel ? oute : g_O1;
    __shared__ float sm1[8];
    __shared__ float sm2[8];
    size_t base = (size_t)blockIdx.x * 1024;
    int t = threadIdx.x;
    float v[4];
    float sum = 0.f;
    #pragma unroll
    for (int i = 0; i < 4; i++) {
        int c = t + i * 256;
        v[i] = in1[base + c] + res[base + c];
        sum += v[i];
    }
    #pragma unroll
    for (int o = 16; o > 0; o >>= 1) sum += __shfl_xor_sync(0xffffffffu, sum, o);
    if ((t & 31) == 0) sm1[t >> 5] = sum;
    __syncthreads();
    sum = 0.f;
    #pragma unroll
    for (int i = 0; i < 8; i++) sum += sm1[i];
    float mean = sum * (1.f / 1024.f);
    float sq = 0.f;
    #pragma unroll
    for (int i = 0; i < 4; i++) { float d = v[i] - mean; sq += d * d; }
    #pragma unroll
    for (int o = 16; o > 0; o >>= 1) sq += __shfl_xor_sync(0xffffffffu, sq, o);
    if ((t & 31) == 0) sm2[t >> 5] = sq;
    __syncthreads();
    sq = 0.f;
    #pragma unroll
    for (int i = 0; i < 8; i++) sq += sm2[i];
    float rstd = rsqrtf(sq * (1.f / 1024.f) + 1e-5f);
    #pragma unroll
    for (int i = 0; i < 4; i++) {
        int c = t + i * 256;
        out[base + c] = (v[i] - mean) * rstd * g[c] + bb[c];
    }
}

// ---------------------------------------------------------------------------
extern "C" void kernel_launch(void* const* d_in, const int* in_sizes, int n_in,
                              void* d_out, int out_size) {
    const float* Xq  = (const float*)d_in[0];
    const float* Xk  = (const float*)d_in[1];
    const float* Xv  = (const float*)d_in[2];
    const float* Wq1 = (const float*)d_in[3];
    const float* Wq2 = (const float*)d_in[4];
    const float* Wk1 = (const float*)d_in[5];
    const float* Wk2 = (const float*)d_in[6];
    const float* Wv  = (const float*)d_in[7];
    const float* Wfc = (const float*)d_in[8];
    const float* Am  = (const float*)d_in[9];
    const float* lng = (const float*)d_in[10];
    const float* lnb = (const float*)d_in[11];
    float* out = (float*)d_out;
    // attn_VV is the second tuple element; place after `outputs`.
    size_t attn_off = (out_size > OUT_MAIN) ? (size_t)(out_size - OUT_MAIN) : 0;
    float* attn = out + attn_off;

    k_proj1<<<2048, dim3(32, 8)>>>(Xq, Wq1, 0);
    k_proj1<<<2048, dim3(32, 8)>>>(Xk, Wk1, 1);
    k_proj2<<<1024, 256>>>(Wq2, 0);
    k_proj2<<<1024, 256>>>(Wk2, 1);
    k_sgemm<<<dim3(8, 128), 256>>>(Xv, Wv, 0);          // V = Xv @ Wv
    k_scores<<<dim3(32, 128), 256>>>(Am, attn);          // raw scores -> attn buf
    k_softmax<<<8192, 256>>>(attn);                      // softmax over S, in place
    k_vv<<<128, 256>>>(attn);                            // VV = attn @ V
    k_stage2<<<dim3(16, 128), 128>>>(Am);                // fused scores2/softmax/VVV
    k_ln<<<16384, 256>>>(Xq, lng, lnb, nullptr, 0);      // out1 = LN(VVV + Xq)
    k_sgemm<<<dim3(8, 128), 256>>>(nullptr, Wfc, 1);     // out2 = out1 @ Wfc
    k_ln<<<16384, 256>>>(nullptr, lng, lnb, out, 1);     // out = LN(out2 + out1)
}

// round 4
// speedup vs baseline: 1.5837x; 1.5837x over previous
#include <cuda_runtime.h>
#include <cuda_bf16.h>
#include <cstdint>

// Problem constants
#define Bq   8
#define Sq   2048
#define Dq   1024
#define Hq   16
#define DHq  64
#define Mrows (Bq*Sq)        // 16384
#define BHn   (Bq*Hq)        // 128
#define OUT_MAIN (Mrows*Dq)  // 16777216 floats of `outputs`

__device__ float g_Tq[Mrows*32];
__device__ float g_Tk[Mrows*32];
__device__ float g_Q [Mrows*Dq];
__device__ float g_K [Mrows*Dq];
__device__ float g_V [Mrows*Dq];
__device__ float g_VV[BHn*DHq*DHq];
__device__ float g_VVV[Mrows*Dq];
__device__ float g_O1[Mrows*Dq];
__device__ float g_O2[Mrows*Dq];

// bf16 split buffers for tensor-core GEMMs (reused by both GEMMs)
__device__ __align__(128) __nv_bfloat16 g_Ah[Mrows*Dq];
__device__ __align__(128) __nv_bfloat16 g_Al[Mrows*Dq];
__device__ __align__(128) __nv_bfloat16 g_Bh[Dq*Dq];   // transposed weight [n][k]
__device__ __align__(128) __nv_bfloat16 g_Bl[Dq*Dq];

// ===========================================================================
// PTX helpers (all sm_80/90 baseline — compile under compute_103)
// ===========================================================================
__device__ __forceinline__ uint32_t smem_u32(const void* p) {
    uint32_t a;
    asm("{ .reg .u64 t; cvta.to.shared.u64 t, %1; cvt.u32.u64 %0, t; }" : "=r"(a) : "l"(p));
    return a;
}
__device__ __forceinline__ void cpa16(uint32_t s, const void* g) {
    asm volatile("cp.async.cg.shared.global [%0], [%1], 16;" :: "r"(s), "l"(g));
}
__device__ __forceinline__ void cpa_commit() {
    asm volatile("cp.async.commit_group;" ::: "memory");
}
__device__ __forceinline__ void cpa_wait1() {
    asm volatile("cp.async.wait_group 1;" ::: "memory");
}
__device__ __forceinline__ void ldsm4(uint32_t* r, uint32_t addr) {
    asm volatile("ldmatrix.sync.aligned.m8n8.x4.shared.b16 {%0,%1,%2,%3}, [%4];"
                 : "=r"(r[0]), "=r"(r[1]), "=r"(r[2]), "=r"(r[3]) : "r"(addr));
}
__device__ __forceinline__ void mma16816(float* c, const uint32_t* a, const uint32_t* b) {
    asm volatile(
        "mma.sync.aligned.m16n8k16.row.col.f32.bf16.bf16.f32 "
        "{%0,%1,%2,%3}, {%4,%5,%6,%7}, {%8,%9}, {%0,%1,%2,%3};"
        : "+f"(c[0]), "+f"(c[1]), "+f"(c[2]), "+f"(c[3])
        : "r"(a[0]), "r"(a[1]), "r"(a[2]), "r"(a[3]), "r"(b[0]), "r"(b[1]));
}

// ===========================================================================
// HMMA GEMM: C[16384,1024] = A[16384,1024] @ W[1024,1024]  (bf16x3)
// A as g_Ah/g_Al row-major [m][k]; W as g_Bh/g_Bl transposed [n][k].
// CTA 128x128, 256 threads (8 warps of 64x32), K-chunk 32, 2-stage cp.async.
// ===========================================================================
#define GP 40                      // smem row pitch in bf16 elems (padded)
#define ST_AH 0
#define ST_AL 10240                // byte offsets within a stage
#define ST_BH 20480
#define ST_BL 30720
#define ST_BYTES 40960
#define HG_SMEM (2*ST_BYTES)

__device__ __forceinline__ void hg_load_stage(uint32_t sb, int st,
                                              const __nv_bfloat16* gAh, const __nv_bfloat16* gAl,
                                              const __nv_bfloat16* gBh, const __nv_bfloat16* gBl,
                                              int m0, int n0, int kc, int tid) {
    uint32_t base = sb + st * ST_BYTES;
    #pragma unroll
    for (int i = 0; i < 2; i++) {
        int ch = tid + i * 256;           // 0..511
        int row = ch >> 2, c4 = ch & 3;
        uint32_t so = (uint32_t)(row * GP + c4 * 8) * 2;
        size_t goA = (size_t)(m0 + row) * Dq + kc + c4 * 8;
        size_t goB = (size_t)(n0 + row) * Dq + kc + c4 * 8;
        cpa16(base + ST_AH + so, gAh + goA);
        cpa16(base + ST_AL + so, gAl + goA);
        cpa16(base + ST_BH + so, gBh + goB);
        cpa16(base + ST_BL + so, gBl + goB);
    }
}

__global__ void __launch_bounds__(256, 1) k_hgemm(float* __restrict__ C) {
    extern __shared__ char smem[];
    uint32_t sb = smem_u32(smem);
    int tid = threadIdx.x;
    int lane = tid & 31, warp = tid >> 5;
    int wm = warp & 1, wn = warp >> 1;      // warp tile: rows wm*64, cols wn*32
    int m0 = blockIdx.y * 128;
    int n0 = blockIdx.x * 128;

    const __nv_bfloat16* gAh = g_Ah;
    const __nv_bfloat16* gAl = g_Al;
    const __nv_bfloat16* gBh = g_Bh;
    const __nv_bfloat16* gBl = g_Bl;

    float acc[4][4][4];
    #pragma unroll
    for (int i = 0; i < 4; i++)
        #pragma unroll
        for (int j = 0; j < 4; j++)
            #pragma unroll
            for (int k = 0; k < 4; k++) acc[i][j][k] = 0.f;

    hg_load_stage(sb, 0, gAh, gAl, gBh, gBl, m0, n0, 0, tid);
    cpa_commit();
    hg_load_stage(sb, 1, gAh, gAl, gBh, gBl, m0, n0, 32, tid);
    cpa_commit();
    cpa_wait1();
    __syncthreads();

    // per-lane ldmatrix address offsets (in elems)
    int aRow = lane & 15, aKo = (lane >> 4) << 3;                 // A: row, k-offset
    int bRow = (lane & 7) + ((lane >> 4) << 3);                   // B: n-offset
    int bKo = ((lane >> 3) & 1) << 3;                             // B: k-offset

    for (int c = 0; c < 32; c++) {
        int st = c & 1;
        uint32_t s0 = sb + st * ST_BYTES;
        #pragma unroll
        for (int kh = 0; kh < 2; kh++) {
            uint32_t ah[4][4], al[4][4], bh[4][2], bl[4][2];
            #pragma unroll
            for (int mt = 0; mt < 4; mt++) {
                uint32_t off = (uint32_t)((wm * 64 + mt * 16 + aRow) * GP + kh * 16 + aKo) * 2;
                ldsm4(ah[mt], s0 + ST_AH + off);
                ldsm4(al[mt], s0 + ST_AL + off);
            }
            #pragma unroll
            for (int nt2 = 0; nt2 < 2; nt2++) {
                uint32_t off = (uint32_t)((wn * 32 + nt2 * 16 + bRow) * GP + kh * 16 + bKo) * 2;
                uint32_t r[4];
                ldsm4(r, s0 + ST_BH + off);
                bh[nt2*2][0] = r[0]; bh[nt2*2][1] = r[1];
                bh[nt2*2+1][0] = r[2]; bh[nt2*2+1][1] = r[3];
                ldsm4(r, s0 + ST_BL + off);
                bl[nt2*2][0] = r[0]; bl[nt2*2][1] = r[1];
                bl[nt2*2+1][0] = r[2]; bl[nt2*2+1][1] = r[3];
            }
            // product order hh, hl, lh — 16 independent tiles between acc reuses
            #pragma unroll
            for (int mt = 0; mt < 4; mt++)
                #pragma unroll
                for (int nt = 0; nt < 4; nt++) mma16816(acc[mt][nt], ah[mt], bh[nt]);
            #pragma unroll
            for (int mt = 0; mt < 4; mt++)
                #pragma unroll
                for (int nt = 0; nt < 4; nt++) mma16816(acc[mt][nt], ah[mt], bl[nt]);
            #pragma unroll
            for (int mt = 0; mt < 4; mt++)
                #pragma unroll
                for (int nt = 0; nt < 4; nt++) mma16816(acc[mt][nt], al[mt], bh[nt]);
        }
        __syncthreads();
        if (c + 2 < 32)
            hg_load_stage(sb, st, gAh, gAl, gBh, gBl, m0, n0, (c + 2) * 32, tid);
        cpa_commit();
        cpa_wait1();
        __syncthreads();
    }

    // epilogue
    #pragma unroll
    for (int mt = 0; mt < 4; mt++) {
        int r0 = m0 + wm * 64 + mt * 16 + (lane >> 2);
        #pragma unroll
        for (int nt = 0; nt < 4; nt++) {
            int col = n0 + wn * 32 + nt * 8 + (lane & 3) * 2;
            *(float2*)(C + (size_t)r0 * Dq + col)       = make_float2(acc[mt][nt][0], acc[mt][nt][1]);
            *(float2*)(C + (size_t)(r0 + 8) * Dq + col) = make_float2(acc[mt][nt][2], acc[mt][nt][3]);
        }
    }
}

// ===========================================================================
// fp32 -> bf16 hi/lo split into g_Ah/g_Al (device globals — NO host-passed
// symbol addresses; on GB300 ATS those silently write host memory).
// ===========================================================================
__global__ void k_split(const float* __restrict__ x) {
    size_t i = ((size_t)blockIdx.x * 256 + threadIdx.x) * 4;
    float4 v = *(const float4*)(x + i);
    __nv_bfloat16 h0 = __float2bfloat16(v.x), h1 = __float2bfloat16(v.y);
    __nv_bfloat16 h2 = __float2bfloat16(v.z), h3 = __float2bfloat16(v.w);
    __nv_bfloat16 l0 = __float2bfloat16(v.x - __bfloat162float(h0));
    __nv_bfloat16 l1 = __float2bfloat16(v.y - __bfloat162float(h1));
    __nv_bfloat16 l2 = __float2bfloat16(v.z - __bfloat162float(h2));
    __nv_bfloat16 l3 = __float2bfloat16(v.w - __bfloat162float(h3));
    *(__nv_bfloat162*)(g_Ah + i)     = __nv_bfloat162(h0, h1);
    *(__nv_bfloat162*)(g_Ah + i + 2) = __nv_bfloat162(h2, h3);
    *(__nv_bfloat162*)(g_Al + i)     = __nv_bfloat162(l0, l1);
    *(__nv_bfloat162*)(g_Al + i + 2) = __nv_bfloat162(l2, l3);
}

// ===========================================================================
// fp32 W[k][n] -> transposed bf16 hi/lo Wt[n][k]  (1024x1024)
// ===========================================================================
__global__ void k_splitT(const float* __restrict__ W) {
    __shared__ float t[32][33];
    int tx = threadIdx.x, ty = threadIdx.y;   // block (32,8)
    int bx = blockIdx.x, by = blockIdx.y;
    #pragma unroll
    for (int i = 0; i < 4; i++)
        t[ty + i*8][tx] = W[(size_t)(by*32 + ty + i*8) * Dq + bx*32 + tx];
    __syncthreads();
    #pragma unroll
    for (int i = 0; i < 4; i++) {
        float v = t[tx][ty + i*8];
        __nv_bfloat16 h = __float2bfloat16(v);
        __nv_bfloat16 l = __float2bfloat16(v - __bfloat162float(h));
        size_t o = (size_t)(bx*32 + ty + i*8) * Dq + by*32 + tx;
        g_Bh[o] = h;
        g_Bl[o] = l;
    }
}

// ---------------------------------------------------------------------------
// proj1: T = X @ W1   (X: [16384,1024], W1: [1024,32])
// ---------------------------------------------------------------------------
__global__ void k_proj1(const float* __restrict__ X, const float* __restrict__ W, int sel) {
    __shared__ float As[8][1024];
    float* T = sel ? g_Tk : g_Tq;
    int tx = threadIdx.x, ty = threadIdx.y;
    int t = ty * 32 + tx;
    int row0 = blockIdx.x * 8;
    #pragma unroll
    for (int i = 0; i < 32; i++) {
        int idx = t + i * 256;
        As[idx >> 10][idx & 1023] = X[(size_t)(row0 + (idx >> 10)) * 1024 + (idx & 1023)];
    }
    __syncthreads();
    float sum = 0.f;
    #pragma unroll 8
    for (int k = 0; k < 1024; k++) sum += As[ty][k] * W[k * 32 + tx];
    T[(size_t)(row0 + ty) * 32 + tx] = sum;
}

// ---------------------------------------------------------------------------
// proj2: O = T @ W2   (T: [16384,32], W2: [32,1024])
// ---------------------------------------------------------------------------
__global__ void k_proj2(const float* __restrict__ W2, int sel) {
    __shared__ float ts[16][32];
    const float* T = sel ? g_Tk : g_Tq;
    float* O = sel ? g_K : g_Q;
    int t = threadIdx.x;
    int row0 = blockIdx.x * 16;
    for (int i = t; i < 512; i += 256) ts[i >> 5][i & 31] = T[(size_t)row0 * 32 + i];
    __syncthreads();
    float acc[16][4];
    #pragma unroll
    for (int r = 0; r < 16; r++)
        #pragma unroll
        for (int j = 0; j < 4; j++) acc[r][j] = 0.f;
    for (int k = 0; k < 32; k++) {
        float wv[4];
        #pragma unroll
        for (int j = 0; j < 4; j++) wv[j] = W2[k * 1024 + t + j * 256];
        #pragma unroll
        for (int r = 0; r < 16; r++) {
            float tv = ts[r][k];
            #pragma unroll
            for (int j = 0; j < 4; j++) acc[r][j] += tv * wv[j];
        }
    }
    #pragma unroll
    for (int r = 0; r < 16; r++)
        #pragma unroll
        for (int j = 0; j < 4; j++)
            O[(size_t)(row0 + r) * 1024 + t + j * 256] = acc[r][j];
}

// ---------------------------------------------------------------------------
// scores: attn[b,h,d,s] = scale * sum_f A[f,d] * K[b,h,s,f]   (raw scores)
// ---------------------------------------------------------------------------
__global__ void k_scores(const float* __restrict__ Amat, float* __restrict__ attn) {
    __shared__ float Asm[64][64];
    __shared__ float Ksm[64][65];
    int bh = blockIdx.y;
    int b = bh >> 4, h = bh & 15;
    int s0 = blockIdx.x * 64;
    int t = threadIdx.x;
    for (int i = t; i < 4096; i += 256) Asm[i >> 6][i & 63] = Amat[i];
    for (int i = t; i < 4096; i += 256) {
        int sl = i >> 6, f = i & 63;
        Ksm[sl][f] = g_K[(size_t)(b * Sq + s0 + sl) * 1024 + h * 64 + f];
    }
    __syncthreads();
    int sl = t & 63, dg = t >> 6;
    float acc[16];
    #pragma unroll
    for (int i = 0; i < 16; i++) acc[i] = 0.f;
    #pragma unroll 4
    for (int fb = 0; fb < 64; fb += 16) {
        float kr[16];
        #pragma unroll
        for (int q = 0; q < 16; q++) kr[q] = Ksm[sl][fb + q];
        #pragma unroll
        for (int dd = 0; dd < 16; dd++) {
            int d = dg * 16 + dd;
            float s = 0.f;
            #pragma unroll
            for (int q = 0; q < 16; q++) s += Asm[fb + q][d] * kr[q];
            acc[dd] += s;
        }
    }
    #pragma unroll
    for (int dd = 0; dd < 16; dd++) {
        int d = dg * 16 + dd;
        attn[((size_t)(bh * 64 + d)) * Sq + s0 + sl] = acc[dd] * 0.125f;
    }
}

// ---------------------------------------------------------------------------
// softmax over s (row length 2048), in place.
// ---------------------------------------------------------------------------
__global__ void k_softmax(float* __restrict__ attn) {
    __shared__ float smx[8];
    __shared__ float sms[8];
    float* p = attn + (size_t)blockIdx.x * Sq;
    int t = threadIdx.x;
    float v[8];
    float m = -1e30f;
    #pragma unroll
    for (int i = 0; i < 8; i++) { v[i] = p[t + i * 256]; m = fmaxf(m, v[i]); }
    #pragma unroll
    for (int o = 16; o > 0; o >>= 1) m = fmaxf(m, __shfl_xor_sync(0xffffffffu, m, o));
    if ((t & 31) == 0) smx[t >> 5] = m;
    __syncthreads();
    m = smx[0];
    #pragma unroll
    for (int i = 1; i < 8; i++) m = fmaxf(m, smx[i]);
    float l = 0.f;
    #pragma unroll
    for (int i = 0; i < 8; i++) { v[i] = __expf(v[i] - m); l += v[i]; }
    #pragma unroll
    for (int o = 16; o > 0; o >>= 1) l += __shfl_xor_sync(0xffffffffu, l, o);
    if ((t & 31) == 0) sms[t >> 5] = l;
    __syncthreads();
    l = 0.f;
    #pragma unroll
    for (int i = 0; i < 8; i++) l += sms[i];
    float inv = 1.f / l;
    #pragma unroll
    for (int i = 0; i < 8; i++) p[t + i * 256] = v[i] * inv;
}

// ---------------------------------------------------------------------------
// VV[bh][d][f] = sum_s attn[bh,d,s] * V[b,s,h*64+f]
// ---------------------------------------------------------------------------
__global__ void k_vv(const float* __restrict__ attn) {
    __shared__ float At[64][65];
    __shared__ float Vs[64][65];
    int bh = blockIdx.x;
    int b = bh >> 4, h = bh & 15;
    int t = threadIdx.x;
    int tr = t >> 4, tc = t & 15;
    float acc[4][4];
    #pragma unroll
    for (int i = 0; i < 4; i++)
        #pragma unroll
        for (int j = 0; j < 4; j++) acc[i][j] = 0.f;
    for (int sc0 = 0; sc0 < Sq; sc0 += 64) {
        for (int i = t; i < 4096; i += 256) {
            int d = i >> 6, ss = i & 63;
            At[d][ss] = attn[((size_t)(bh * 64 + d)) * Sq + sc0 + ss];
        }
        for (int i = t; i < 4096; i += 256) {
            int ss = i >> 6, f = i & 63;
            Vs[ss][f] = g_V[(size_t)(b * Sq + sc0 + ss) * 1024 + h * 64 + f];
        }
        __syncthreads();
        #pragma unroll 8
        for (int ss = 0; ss < 64; ss++) {
            float av[4], bv[4];
            #pragma unroll
            for (int i = 0; i < 4; i++) av[i] = At[tr * 4 + i][ss];
            #pragma unroll
            for (int j = 0; j < 4; j++) bv[j] = Vs[ss][tc * 4 + j];
            #pragma unroll
            for (int i = 0; i < 4; i++)
                #pragma unroll
                for (int j = 0; j < 4; j++) acc[i][j] += av[i] * bv[j];
        }
        __syncthreads();
    }
    #pragma unroll
    for (int i = 0; i < 4; i++)
        #pragma unroll
        for (int j = 0; j < 4; j++)
            g_VV[(size_t)bh * 4096 + (tr * 4 + i) * 64 + tc * 4 + j] = acc[i][j];
}

// ---------------------------------------------------------------------------
// stage 2 fused: scores2 = Q@A^T * scale; softmax over d (64); VVV = p @ VV
// ---------------------------------------------------------------------------
__global__ void k_stage2(const float* __restrict__ Amat) {
    __shared__ float Asm[64][64];
    __shared__ float VVs[64][64];
    int bh = blockIdx.y;
    int b = bh >> 4, h = bh & 15;
    int s0 = blockIdx.x * 128;
    int t = threadIdx.x;
    for (int i = t; i < 4096; i += 128) Asm[i >> 6][i & 63] = Amat[i];
    for (int i = t; i < 4096; i += 128) VVs[i >> 6][i & 63] = g_VV[(size_t)bh * 4096 + i];
    __syncthreads();
    int s = s0 + t;
    const float* Qrow = g_Q + (size_t)(b * Sq + s) * 1024 + h * 64;
    float qr[64];
    #pragma unroll
    for (int f4 = 0; f4 < 64; f4 += 4) {
        float4 q = *(const float4*)(Qrow + f4);
        qr[f4] = q.x; qr[f4 + 1] = q.y; qr[f4 + 2] = q.z; qr[f4 + 3] = q.w;
    }
    float out[64];
    #pragma unroll
    for (int f = 0; f < 64; f++) out[f] = 0.f;
    float m = -1e30f, l = 0.f;
    for (int d = 0; d < 64; d++) {
        float sc = 0.f;
        #pragma unroll
        for (int f = 0; f < 64; f++) sc += qr[f] * Asm[d][f];
        sc *= 0.125f;
        float mn = fmaxf(m, sc);
        float fac = __expf(m - mn);
        float pp = __expf(sc - mn);
        l = l * fac + pp;
        #pragma unroll
        for (int f = 0; f < 64; f++) out[f] = out[f] * fac + pp * VVs[d][f];
        m = mn;
    }
    float inv = 1.f / l;
    float* Orow = g_VVV + ((size_t)bh * Sq + s) * 64;
    #pragma unroll
    for (int f = 0; f < 64; f += 4)
        *(float4*)(Orow + f) = make_float4(out[f] * inv, out[f+1] * inv,
                                           out[f+2] * inv, out[f+3] * inv);
}

// ---------------------------------------------------------------------------
// LayerNorm over last dim (1024), x = in1 + res.
// ---------------------------------------------------------------------------
__global__ void k_ln(const float* __restrict__ rese, const float* __restrict__ g,
                     const float* __restrict__ bb, float* __restrict__ oute, int sel) {
    const float* in1 = sel ? g_O2 : g_VVV;
    const float* res = sel ? g_O1 : rese;
    float* out = sel ? oute : g_O1;
    __shared__ float sm1[8];
    __shared__ float sm2[8];
    size_t base = (size_t)blockIdx.x * 1024;
    int t = threadIdx.x;
    float v[4];
    float sum = 0.f;
    #pragma unroll
    for (int i = 0; i < 4; i++) {
        int c = t + i * 256;
        v[i] = in1[base + c] + res[base + c];
        sum += v[i];
    }
    #pragma unroll
    for (int o = 16; o > 0; o >>= 1) sum += __shfl_xor_sync(0xffffffffu, sum, o);
    if ((t & 31) == 0) sm1[t >> 5] = sum;
    __syncthreads();
    sum = 0.f;
    #pragma unroll
    for (int i = 0; i < 8; i++) sum += sm1[i];
    float mean = sum * (1.f / 1024.f);
    float sq = 0.f;
    #pragma unroll
    for (int i = 0; i < 4; i++) { float d = v[i] - mean; sq += d * d; }
    #pragma unroll
    for (int o = 16; o > 0; o >>= 1) sq += __shfl_xor_sync(0xffffffffu, sq, o);
    if ((t & 31) == 0) sm2[t >> 5] = sq;
    __syncthreads();
    sq = 0.f;
    #pragma unroll
    for (int i = 0; i < 8; i++) sq += sm2[i];
    float rstd = rsqrtf(sq * (1.f / 1024.f) + 1e-5f);
    #pragma unroll
    for (int i = 0; i < 4; i++) {
        int c = t + i * 256;
        out[base + c] = (v[i] - mean) * rstd * g[c] + bb[c];
    }
}

// ===========================================================================
// Host side
// ===========================================================================
extern "C" void kernel_launch(void* const* d_in, const int* in_sizes, int n_in,
                              void* d_out, int out_size) {
    const float* Xq  = (const float*)d_in[0];
    const float* Xk  = (const float*)d_in[1];
    const float* Xv  = (const float*)d_in[2];
    const float* Wq1 = (const float*)d_in[3];
    const float* Wq2 = (const float*)d_in[4];
    const float* Wk1 = (const float*)d_in[5];
    const float* Wk2 = (const float*)d_in[6];
    const float* Wv  = (const float*)d_in[7];
    const float* Wfc = (const float*)d_in[8];
    const float* Am  = (const float*)d_in[9];
    const float* lng = (const float*)d_in[10];
    const float* lnb = (const float*)d_in[11];
    float* out = (float*)d_out;
    size_t attn_off = (out_size > OUT_MAIN) ? (size_t)(out_size - OUT_MAIN) : 0;
    float* attn = out + attn_off;

    void *pV, *pO1, *pO2;
    cudaGetSymbolAddress(&pV,  g_V);
    cudaGetSymbolAddress(&pO1, g_O1);
    cudaGetSymbolAddress(&pO2, g_O2);

    cudaFuncSetAttribute(k_hgemm, cudaFuncAttributeMaxDynamicSharedMemorySize, HG_SMEM);

    k_proj1<<<2048, dim3(32, 8)>>>(Xq, Wq1, 0);
    k_proj1<<<2048, dim3(32, 8)>>>(Xk, Wk1, 1);
    k_proj2<<<1024, 256>>>(Wq2, 0);
    k_proj2<<<1024, 256>>>(Wk2, 1);

    // V = Xv @ Wv on tensor cores (bf16x3, mma.sync)
    k_split<<<16384, 256>>>(Xv);
    k_splitT<<<dim3(32, 32), dim3(32, 8)>>>(Wv);
    k_hgemm<<<dim3(8, 128), 256, HG_SMEM>>>((float*)pV);

    k_scores<<<dim3(32, 128), 256>>>(Am, attn);
    k_softmax<<<8192, 256>>>(attn);
    k_vv<<<128, 256>>>(attn);
    k_stage2<<<dim3(16, 128), 128>>>(Am);
    k_ln<<<16384, 256>>>(Xq, lng, lnb, nullptr, 0);      // out1 = LN(VVV + Xq)

    // out2 = out1 @ Wfc on tensor cores (bf16x3, mma.sync)
    k_split<<<16384, 256>>>((const float*)pO1);
    k_splitT<<<dim3(32, 32), dim3(32, 8)>>>(Wfc);
    k_hgemm<<<dim3(8, 128), 256, HG_SMEM>>>((float*)pO2);

    k_ln<<<16384, 256>>>(nullptr, lng, lnb, out, 1);     // out = LN(out2 + out1)
}

// round 5
// speedup vs baseline: 1.9219x; 1.2135x over previous
#include <cuda_runtime.h>
#include <cuda_bf16.h>
#include <cstdint>

// Problem constants
#define Bq   8
#define Sq   2048
#define Dq   1024
#define Hq   16
#define DHq  64
#define Mrows (Bq*Sq)        // 16384
#define BHn   (Bq*Hq)        // 128
#define OUT_MAIN (Mrows*Dq)  // 16777216 floats of `outputs`

__device__ float g_Tq[Mrows*32];
__device__ float g_Tk[Mrows*32];
__device__ float g_Q [Mrows*Dq];
__device__ float g_K [Mrows*Dq];
__device__ float g_V [Mrows*Dq];
__device__ float g_VV[BHn*DHq*DHq];
__device__ float g_VVV[Mrows*Dq];
__device__ float g_O1[Mrows*Dq];
__device__ float g_O2[Mrows*Dq];

// bf16 split buffers for tensor-core GEMMs (reused by both GEMMs)
__device__ __align__(128) __nv_bfloat16 g_Ah[Mrows*Dq];
__device__ __align__(128) __nv_bfloat16 g_Al[Mrows*Dq];
__device__ __align__(128) __nv_bfloat16 g_Bh[Dq*Dq];   // transposed weight [n][k]
__device__ __align__(128) __nv_bfloat16 g_Bl[Dq*Dq];

// ===========================================================================
// PTX helpers (sm_80/90 baseline — compile under compute_103)
// ===========================================================================
__device__ __forceinline__ uint32_t smem_u32(const void* p) {
    uint32_t a;
    asm("{ .reg .u64 t; cvta.to.shared.u64 t, %1; cvt.u32.u64 %0, t; }" : "=r"(a) : "l"(p));
    return a;
}
__device__ __forceinline__ void cpa16(uint32_t s, const void* g) {
    asm volatile("cp.async.cg.shared.global [%0], [%1], 16;" :: "r"(s), "l"(g));
}
__device__ __forceinline__ void cpa_commit() {
    asm volatile("cp.async.commit_group;" ::: "memory");
}
__device__ __forceinline__ void cpa_wait1() {
    asm volatile("cp.async.wait_group 1;" ::: "memory");
}
__device__ __forceinline__ void ldsm4(uint32_t* r, uint32_t addr) {
    asm volatile("ldmatrix.sync.aligned.m8n8.x4.shared.b16 {%0,%1,%2,%3}, [%4];"
                 : "=r"(r[0]), "=r"(r[1]), "=r"(r[2]), "=r"(r[3]) : "r"(addr));
}
__device__ __forceinline__ void mma16816(float* c, const uint32_t* a, const uint32_t* b) {
    asm volatile(
        "mma.sync.aligned.m16n8k16.row.col.f32.bf16.bf16.f32 "
        "{%0,%1,%2,%3}, {%4,%5,%6,%7}, {%8,%9}, {%0,%1,%2,%3};"
        : "+f"(c[0]), "+f"(c[1]), "+f"(c[2]), "+f"(c[3])
        : "r"(a[0]), "r"(a[1]), "r"(a[2]), "r"(a[3]), "r"(b[0]), "r"(b[1]));
}

// ===========================================================================
// HMMA GEMM: C[16384,1024] = A @ W  (bf16x3), 512 threads, 16 warps of 32x32.
// ===========================================================================
#define GP 40
#define ST_AH 0
#define ST_AL 10240
#define ST_BH 20480
#define ST_BL 30720
#define ST_BYTES 40960
#define HG_SMEM (2*ST_BYTES)

__device__ __forceinline__ void hg_load_stage(uint32_t sb, int st,
                                              int m0, int n0, int kc, int tid) {
    uint32_t base = sb + st * ST_BYTES;
    int row = tid >> 2, c4 = tid & 3;
    uint32_t so = (uint32_t)(row * GP + c4 * 8) * 2;
    size_t goA = (size_t)(m0 + row) * Dq + kc + c4 * 8;
    size_t goB = (size_t)(n0 + row) * Dq + kc + c4 * 8;
    cpa16(base + ST_AH + so, g_Ah + goA);
    cpa16(base + ST_AL + so, g_Al + goA);
    cpa16(base + ST_BH + so, g_Bh + goB);
    cpa16(base + ST_BL + so, g_Bl + goB);
}

__global__ void __launch_bounds__(512, 1) k_hgemm(float* __restrict__ C) {
    extern __shared__ char smem[];
    uint32_t sb = smem_u32(smem);
    int tid = threadIdx.x;
    int lane = tid & 31, w = tid >> 5;
    int wm = w & 3, wn = w >> 2;          // warp tile: rows wm*32, cols wn*32
    int m0 = blockIdx.y * 128;
    int n0 = blockIdx.x * 128;

    float acc[2][4][4];
    #pragma unroll
    for (int i = 0; i < 2; i++)
        #pragma unroll
        for (int j = 0; j < 4; j++)
            #pragma unroll
            for (int k = 0; k < 4; k++) acc[i][j][k] = 0.f;

    hg_load_stage(sb, 0, m0, n0, 0, tid);
    cpa_commit();
    hg_load_stage(sb, 1, m0, n0, 32, tid);
    cpa_commit();
    cpa_wait1();
    __syncthreads();

    int aRow = lane & 15, aKo = (lane >> 4) << 3;
    int bRow = (lane & 7) + ((lane >> 4) << 3);
    int bKo = ((lane >> 3) & 1) << 3;

    for (int c = 0; c < 32; c++) {
        int st = c & 1;
        uint32_t s0 = sb + st * ST_BYTES;
        #pragma unroll
        for (int kh = 0; kh < 2; kh++) {
            uint32_t ah[2][4], al[2][4], bh[4][2], bl[4][2];
            #pragma unroll
            for (int mt = 0; mt < 2; mt++) {
                uint32_t off = (uint32_t)((wm * 32 + mt * 16 + aRow) * GP + kh * 16 + aKo) * 2;
                ldsm4(ah[mt], s0 + ST_AH + off);
                ldsm4(al[mt], s0 + ST_AL + off);
            }
            #pragma unroll
            for (int nt2 = 0; nt2 < 2; nt2++) {
                uint32_t off = (uint32_t)((wn * 32 + nt2 * 16 + bRow) * GP + kh * 16 + bKo) * 2;
                uint32_t r[4];
                ldsm4(r, s0 + ST_BH + off);
                bh[nt2*2][0] = r[0]; bh[nt2*2][1] = r[1];
                bh[nt2*2+1][0] = r[2]; bh[nt2*2+1][1] = r[3];
                ldsm4(r, s0 + ST_BL + off);
                bl[nt2*2][0] = r[0]; bl[nt2*2][1] = r[1];
                bl[nt2*2+1][0] = r[2]; bl[nt2*2+1][1] = r[3];
            }
            #pragma unroll
            for (int mt = 0; mt < 2; mt++)
                #pragma unroll
                for (int nt = 0; nt < 4; nt++) mma16816(acc[mt][nt], ah[mt], bh[nt]);
            #pragma unroll
            for (int mt = 0; mt < 2; mt++)
                #pragma unroll
                for (int nt = 0; nt < 4; nt++) mma16816(acc[mt][nt], ah[mt], bl[nt]);
            #pragma unroll
            for (int mt = 0; mt < 2; mt++)
                #pragma unroll
                for (int nt = 0; nt < 4; nt++) mma16816(acc[mt][nt], al[mt], bh[nt]);
        }
        __syncthreads();
        if (c + 2 < 32)
            hg_load_stage(sb, st, m0, n0, (c + 2) * 32, tid);
        cpa_commit();
        cpa_wait1();
        __syncthreads();
    }

    #pragma unroll
    for (int mt = 0; mt < 2; mt++) {
        int r0 = m0 + wm * 32 + mt * 16 + (lane >> 2);
        #pragma unroll
        for (int nt = 0; nt < 4; nt++) {
            int col = n0 + wn * 32 + nt * 8 + (lane & 3) * 2;
            *(float2*)(C + (size_t)r0 * Dq + col)       = make_float2(acc[mt][nt][0], acc[mt][nt][1]);
            *(float2*)(C + (size_t)(r0 + 8) * Dq + col) = make_float2(acc[mt][nt][2], acc[mt][nt][3]);
        }
    }
}

// ===========================================================================
// fp32 -> bf16 hi/lo split into g_Ah/g_Al (device globals only!)
// ===========================================================================
__global__ void k_split(const float* __restrict__ x) {
    size_t i = ((size_t)blockIdx.x * 256 + threadIdx.x) * 4;
    float4 v = *(const float4*)(x + i);
    __nv_bfloat16 h0 = __float2bfloat16(v.x), h1 = __float2bfloat16(v.y);
    __nv_bfloat16 h2 = __float2bfloat16(v.z), h3 = __float2bfloat16(v.w);
    __nv_bfloat16 l0 = __float2bfloat16(v.x - __bfloat162float(h0));
    __nv_bfloat16 l1 = __float2bfloat16(v.y - __bfloat162float(h1));
    __nv_bfloat16 l2 = __float2bfloat16(v.z - __bfloat162float(h2));
    __nv_bfloat16 l3 = __float2bfloat16(v.w - __bfloat162float(h3));
    *(__nv_bfloat162*)(g_Ah + i)     = __nv_bfloat162(h0, h1);
    *(__nv_bfloat162*)(g_Ah + i + 2) = __nv_bfloat162(h2, h3);
    *(__nv_bfloat162*)(g_Al + i)     = __nv_bfloat162(l0, l1);
    *(__nv_bfloat162*)(g_Al + i + 2) = __nv_bfloat162(l2, l3);
}

// ===========================================================================
// fp32 W[k][n] -> transposed bf16 hi/lo Wt[n][k]  (1024x1024)
// ===========================================================================
__global__ void k_splitT(const float* __restrict__ W) {
    __shared__ float t[32][33];
    int tx = threadIdx.x, ty = threadIdx.y;   // block (32,8)
    int bx = blockIdx.x, by = blockIdx.y;
    #pragma unroll
    for (int i = 0; i < 4; i++)
        t[ty + i*8][tx] = W[(size_t)(by*32 + ty + i*8) * Dq + bx*32 + tx];
    __syncthreads();
    #pragma unroll
    for (int i = 0; i < 4; i++) {
        float v = t[tx][ty + i*8];
        __nv_bfloat16 h = __float2bfloat16(v);
        __nv_bfloat16 l = __float2bfloat16(v - __bfloat162float(h));
        size_t o = (size_t)(bx*32 + ty + i*8) * Dq + by*32 + tx;
        g_Bh[o] = h;
        g_Bl[o] = l;
    }
}

// ---------------------------------------------------------------------------
// proj1: T = X @ W1   (X: [16384,1024], W1: [1024,32])
// block 256, tile 64 rows x 32 cols, k-chunk 64, 8 accumulators/thread.
// ---------------------------------------------------------------------------
__global__ void k_proj1(const float* __restrict__ X, const float* __restrict__ W, int sel) {
    __shared__ float Xs[64][64];
    __shared__ float Ws[64][32];
    float* T = sel ? g_Tk : g_Tq;
    int t = threadIdx.x;
    int row0 = blockIdx.x * 64;
    int tr = t >> 5, tc = t & 31;
    float acc[8];
    #pragma unroll
    for (int i = 0; i < 8; i++) acc[i] = 0.f;
    for (int kc = 0; kc < 1024; kc += 64) {
        #pragma unroll
        for (int i = 0; i < 4; i++) {
            int idx = t + i * 256;
            int r = idx >> 4, c = idx & 15;
            *(float4*)&Xs[r][c*4] = *(const float4*)(X + (size_t)(row0 + r) * 1024 + kc + c*4);
        }
        #pragma unroll
        for (int i = 0; i < 2; i++) {
            int idx = t + i * 256;
            int k = idx >> 3, c = idx & 7;
            *(float4*)&Ws[k][c*4] = *(const float4*)(W + (size_t)(kc + k) * 32 + c*4);
        }
        __syncthreads();
        #pragma unroll
        for (int k = 0; k < 64; k += 4) {
            float w0 = Ws[k][tc], w1 = Ws[k+1][tc], w2 = Ws[k+2][tc], w3 = Ws[k+3][tc];
            #pragma unroll
            for (int i = 0; i < 8; i++) {
                float4 x = *(const float4*)&Xs[tr*8 + i][k];
                acc[i] += x.x*w0 + x.y*w1 + x.z*w2 + x.w*w3;
            }
        }
        __syncthreads();
    }
    #pragma unroll
    for (int i = 0; i < 8; i++)
        T[(size_t)(row0 + tr*8 + i) * 32 + tc] = acc[i];
}

// ---------------------------------------------------------------------------
// proj2: O = T @ W2   (T: [16384,32], W2: [32,1024])
// ---------------------------------------------------------------------------
__global__ void k_proj2(const float* __restrict__ W2, int sel) {
    __shared__ float ts[16][32];
    const float* T = sel ? g_Tk : g_Tq;
    float* O = sel ? g_K : g_Q;
    int t = threadIdx.x;
    int row0 = blockIdx.x * 16;
    for (int i = t; i < 512; i += 256) ts[i >> 5][i & 31] = T[(size_t)row0 * 32 + i];
    __syncthreads();
    float acc[16][4];
    #pragma unroll
    for (int r = 0; r < 16; r++)
        #pragma unroll
        for (int j = 0; j < 4; j++) acc[r][j] = 0.f;
    for (int k = 0; k < 32; k++) {
        float wv[4];
        #pragma unroll
        for (int j = 0; j < 4; j++) wv[j] = W2[k * 1024 + t + j * 256];
        #pragma unroll
        for (int r = 0; r < 16; r++) {
            float tv = ts[r][k];
            #pragma unroll
            for (int j = 0; j < 4; j++) acc[r][j] += tv * wv[j];
        }
    }
    #pragma unroll
    for (int r = 0; r < 16; r++)
        #pragma unroll
        for (int j = 0; j < 4; j++)
            O[(size_t)(row0 + r) * 1024 + t + j * 256] = acc[r][j];
}

// ---------------------------------------------------------------------------
// scores: attn[b,h,d,s] = scale * sum_f A[f,d] * K[b,h,s,f]   (raw scores)
// float4 on both operands; Asm stored [d][f].
// ---------------------------------------------------------------------------
__global__ void k_scores(const float* __restrict__ Amat, float* __restrict__ attn) {
    __shared__ float Asm[64][68];    // [d][f]  (A^T)
    __shared__ float Ksm[64][68];    // [sl][f]
    int bh = blockIdx.y;
    int b = bh >> 4, h = bh & 15;
    int s0 = blockIdx.x * 64;
    int t = threadIdx.x;
    for (int i = t; i < 4096; i += 256) {
        int f = i >> 6, d = i & 63;
        Asm[d][f] = Amat[i];                       // Amat[f*64 + d]
    }
    for (int i = t; i < 4096; i += 256) {
        int sl = i >> 6, f = i & 63;
        Ksm[sl][f] = g_K[(size_t)(b * Sq + s0 + sl) * 1024 + h * 64 + f];
    }
    __syncthreads();
    int sl = t & 63, dg = t >> 6;
    float acc[16];
    #pragma unroll
    for (int i = 0; i < 16; i++) acc[i] = 0.f;
    #pragma unroll
    for (int f4 = 0; f4 < 16; f4++) {
        float4 kv = *(const float4*)&Ksm[sl][f4*4];
        #pragma unroll
        for (int dd = 0; dd < 16; dd++) {
            float4 av = *(const float4*)&Asm[dg*16 + dd][f4*4];
            acc[dd] += kv.x*av.x + kv.y*av.y + kv.z*av.z + kv.w*av.w;
        }
    }
    #pragma unroll
    for (int dd = 0; dd < 16; dd++) {
        int d = dg * 16 + dd;
        attn[((size_t)(bh * 64 + d)) * Sq + s0 + sl] = acc[dd] * 0.125f;
    }
}

// ---------------------------------------------------------------------------
// softmax over s (row length 2048), in place.
// ---------------------------------------------------------------------------
__global__ void k_softmax(float* __restrict__ attn) {
    __shared__ float smx[8];
    __shared__ float sms[8];
    float* p = attn + (size_t)blockIdx.x * Sq;
    int t = threadIdx.x;
    float v[8];
    float m = -1e30f;
    #pragma unroll
    for (int i = 0; i < 8; i++) { v[i] = p[t + i * 256]; m = fmaxf(m, v[i]); }
    #pragma unroll
    for (int o = 16; o > 0; o >>= 1) m = fmaxf(m, __shfl_xor_sync(0xffffffffu, m, o));
    if ((t & 31) == 0) smx[t >> 5] = m;
    __syncthreads();
    m = smx[0];
    #pragma unroll
    for (int i = 1; i < 8; i++) m = fmaxf(m, smx[i]);
    float l = 0.f;
    #pragma unroll
    for (int i = 0; i < 8; i++) { v[i] = __expf(v[i] - m); l += v[i]; }
    #pragma unroll
    for (int o = 16; o > 0; o >>= 1) l += __shfl_xor_sync(0xffffffffu, l, o);
    if ((t & 31) == 0) sms[t >> 5] = l;
    __syncthreads();
    l = 0.f;
    #pragma unroll
    for (int i = 0; i < 8; i++) l += sms[i];
    float inv = 1.f / l;
    #pragma unroll
    for (int i = 0; i < 8; i++) p[t + i * 256] = v[i] * inv;
}

// ---------------------------------------------------------------------------
// VV[bh][d][f] += sum_{s in split} attn[bh,d,s] * V[b,s,h*64+f]
// grid (4 s-splits, 128 bh); atomicAdd into zeroed g_VV.
// ---------------------------------------------------------------------------
__global__ void k_vv(const float* __restrict__ attn) {
    __shared__ float At[64][65];
    __shared__ float Vs[64][65];
    int split = blockIdx.x;
    int bh = blockIdx.y;
    int b = bh >> 4, h = bh & 15;
    int t = threadIdx.x;
    int tr = t >> 4, tc = t & 15;
    float acc[4][4];
    #pragma unroll
    for (int i = 0; i < 4; i++)
        #pragma unroll
        for (int j = 0; j < 4; j++) acc[i][j] = 0.f;
    int sbeg = split * 512;
    for (int sc0 = sbeg; sc0 < sbeg + 512; sc0 += 64) {
        for (int i = t; i < 4096; i += 256) {
            int d = i >> 6, ss = i & 63;
            At[d][ss] = attn[((size_t)(bh * 64 + d)) * Sq + sc0 + ss];
        }
        for (int i = t; i < 4096; i += 256) {
            int ss = i >> 6, f = i & 63;
            Vs[ss][f] = g_V[(size_t)(b * Sq + sc0 + ss) * 1024 + h * 64 + f];
        }
        __syncthreads();
        #pragma unroll 8
        for (int ss = 0; ss < 64; ss++) {
            float av[4], bv[4];
            #pragma unroll
            for (int i = 0; i < 4; i++) av[i] = At[tr * 4 + i][ss];
            #pragma unroll
            for (int j = 0; j < 4; j++) bv[j] = Vs[ss][tc * 4 + j];
            #pragma unroll
            for (int i = 0; i < 4; i++)
                #pragma unroll
                for (int j = 0; j < 4; j++) acc[i][j] += av[i] * bv[j];
        }
        __syncthreads();
    }
    #pragma unroll
    for (int i = 0; i < 4; i++)
        #pragma unroll
        for (int j = 0; j < 4; j++)
            atomicAdd(&g_VV[(size_t)bh * 4096 + (tr * 4 + i) * 64 + tc * 4 + j], acc[i][j]);
}

// ---------------------------------------------------------------------------
// stage 2: two-pass softmax (scores in regs), float4 LDS, halves for output.
// ---------------------------------------------------------------------------
__global__ void k_stage2(const float* __restrict__ Amat) {
    __shared__ float Asm[64][68];   // A[d][f]
    __shared__ float VVs[64][68];   // VV[d][f]
    int bh = blockIdx.y;
    int b = bh >> 4, h = bh & 15;
    int s0 = blockIdx.x * 128;
    int t = threadIdx.x;
    for (int i = t; i < 4096; i += 128) {
        int d = i >> 6, f = i & 63;
        Asm[d][f] = Amat[i];
        VVs[d][f] = g_VV[(size_t)bh * 4096 + i];
    }
    __syncthreads();
    int s = s0 + t;
    const float* Qrow = g_Q + (size_t)(b * Sq + s) * 1024 + h * 64;
    float qr[64];
    #pragma unroll
    for (int f4 = 0; f4 < 64; f4 += 4) {
        float4 q = *(const float4*)(Qrow + f4);
        qr[f4] = q.x; qr[f4+1] = q.y; qr[f4+2] = q.z; qr[f4+3] = q.w;
    }
    // pass 1: raw scores
    float sc[64];
    #pragma unroll
    for (int d = 0; d < 64; d++) {
        float sum = 0.f;
        #pragma unroll
        for (int f4 = 0; f4 < 16; f4++) {
            float4 av = *(const float4*)&Asm[d][f4*4];
            sum += qr[f4*4]*av.x + qr[f4*4+1]*av.y + qr[f4*4+2]*av.z + qr[f4*4+3]*av.w;
        }
        sc[d] = sum * 0.125f;
    }
    float m = sc[0];
    #pragma unroll
    for (int d = 1; d < 64; d++) m = fmaxf(m, sc[d]);
    float l = 0.f;
    #pragma unroll
    for (int d = 0; d < 64; d++) { float e = __expf(sc[d] - m); sc[d] = e; l += e; }
    float inv = 1.f / l;
    // pass 2: out = p @ VV, in two 32-col halves
    float* Orow = g_VVV + ((size_t)bh * Sq + s) * 64;
    #pragma unroll
    for (int half = 0; half < 2; half++) {
        float out[32];
        #pragma unroll
        for (int j = 0; j < 32; j++) out[j] = 0.f;
        #pragma unroll 8
        for (int d = 0; d < 64; d++) {
            float p = sc[d];
            #pragma unroll
            for (int f4 = 0; f4 < 8; f4++) {
                float4 vv = *(const float4*)&VVs[d][half*32 + f4*4];
                out[f4*4]   += p * vv.x;
                out[f4*4+1] += p * vv.y;
                out[f4*4+2] += p * vv.z;
                out[f4*4+3] += p * vv.w;
            }
        }
        #pragma unroll
        for (int j = 0; j < 32; j += 4)
            *(float4*)(Orow + half*32 + j) = make_float4(out[j]*inv, out[j+1]*inv,
                                                         out[j+2]*inv, out[j+3]*inv);
    }
}

// ---------------------------------------------------------------------------
// LayerNorm over last dim (1024), x = in1 + res.
// sel=0: in1=g_VVV, res=Xq, out=g_O1, ALSO emits bf16 hi/lo split to g_Ah/g_Al.
// sel=1: in1=g_O2,  res=g_O1, out=d_out.
// ---------------------------------------------------------------------------
__global__ void k_ln(const float* __restrict__ rese, const float* __restrict__ g,
                     const float* __restrict__ bb, float* __restrict__ oute, int sel) {
    const float* in1 = sel ? g_O2 : g_VVV;
    const float* res = sel ? g_O1 : rese;
    float* out = sel ? oute : g_O1;
    __shared__ float sm1[8];
    __shared__ float sm2[8];
    size_t base = (size_t)blockIdx.x * 1024;
    int t = threadIdx.x;
    float v[4];
    float sum = 0.f;
    #pragma unroll
    for (int i = 0; i < 4; i++) {
        int c = t + i * 256;
        v[i] = in1[base + c] + res[base + c];
        sum += v[i];
    }
    #pragma unroll
    for (int o = 16; o > 0; o >>= 1) sum += __shfl_xor_sync(0xffffffffu, sum, o);
    if ((t & 31) == 0) sm1[t >> 5] = sum;
    __syncthreads();
    sum = 0.f;
    #pragma unroll
    for (int i = 0; i < 8; i++) sum += sm1[i];
    float mean = sum * (1.f / 1024.f);
    float sq = 0.f;
    #pragma unroll
    for (int i = 0; i < 4; i++) { float d = v[i] - mean; sq += d * d; }
    #pragma unroll
    for (int o = 16; o > 0; o >>= 1) sq += __shfl_xor_sync(0xffffffffu, sq, o);
    if ((t & 31) == 0) sm2[t >> 5] = sq;
    __syncthreads();
    sq = 0.f;
    #pragma unroll
    for (int i = 0; i < 8; i++) sq += sm2[i];
    float rstd = rsqrtf(sq * (1.f / 1024.f) + 1e-5f);
    #pragma unroll
    for (int i = 0; i < 4; i++) {
        int c = t + i * 256;
        float o = (v[i] - mean) * rstd * g[c] + bb[c];
        out[base + c] = o;
        if (sel == 0) {
            __nv_bfloat16 h = __float2bfloat16(o);
            g_Ah[base + c] = h;
            g_Al[base + c] = __float2bfloat16(o - __bfloat162float(h));
        }
    }
}

// ===========================================================================
// Host side
// ===========================================================================
extern "C" void kernel_launch(void* const* d_in, const int* in_sizes, int n_in,
                              void* d_out, int out_size) {
    const float* Xq  = (const float*)d_in[0];
    const float* Xk  = (const float*)d_in[1];
    const float* Xv  = (const float*)d_in[2];
    const float* Wq1 = (const float*)d_in[3];
    const float* Wq2 = (const float*)d_in[4];
    const float* Wk1 = (const float*)d_in[5];
    const float* Wk2 = (const float*)d_in[6];
    const float* Wv  = (const float*)d_in[7];
    const float* Wfc = (const float*)d_in[8];
    const float* Am  = (const float*)d_in[9];
    const float* lng = (const float*)d_in[10];
    const float* lnb = (const float*)d_in[11];
    float* out = (float*)d_out;
    size_t attn_off = (out_size > OUT_MAIN) ? (size_t)(out_size - OUT_MAIN) : 0;
    float* attn = out + attn_off;

    void *pV, *pO2, *pVV;
    cudaGetSymbolAddress(&pV,  g_V);
    cudaGetSymbolAddress(&pO2, g_O2);
    cudaGetSymbolAddress(&pVV, g_VV);

    cudaFuncSetAttribute(k_hgemm, cudaFuncAttributeMaxDynamicSharedMemorySize, HG_SMEM);

    k_proj1<<<256, 256>>>(Xq, Wq1, 0);
    k_proj1<<<256, 256>>>(Xk, Wk1, 1);
    k_proj2<<<1024, 256>>>(Wq2, 0);
    k_proj2<<<1024, 256>>>(Wk2, 1);

    // V = Xv @ Wv on tensor cores (bf16x3, mma.sync)
    k_split<<<16384, 256>>>(Xv);
    k_splitT<<<dim3(32, 32), dim3(32, 8)>>>(Wv);
    k_hgemm<<<dim3(8, 128), 512, HG_SMEM>>>((float*)pV);

    k_scores<<<dim3(32, 128), 256>>>(Am, attn);
    k_softmax<<<8192, 256>>>(attn);
    cudaMemsetAsync(pVV, 0, (size_t)BHn * DHq * DHq * sizeof(float));
    k_vv<<<dim3(4, 128), 256>>>(attn);
    k_stage2<<<dim3(16, 128), 128>>>(Am);
    k_ln<<<16384, 256>>>(Xq, lng, lnb, nullptr, 0);      // out1 = LN(VVV+Xq) + bf16 split

    // out2 = out1 @ Wfc on tensor cores (bf16x3, mma.sync)
    k_splitT<<<dim3(32, 32), dim3(32, 8)>>>(Wfc);
    k_hgemm<<<dim3(8, 128), 512, HG_SMEM>>>((float*)pO2);

    k_ln<<<16384, 256>>>(nullptr, lng, lnb, out, 1);     // out = LN(out2 + out1)
}

// round 6
// speedup vs baseline: 2.8247x; 1.4698x over previous
#include <cuda_runtime.h>
#include <cuda_fp16.h>
#include <cstdint>

// Problem constants
#define Bq   8
#define Sq   2048
#define Dq   1024
#define Hq   16
#define DHq  64
#define Mrows (Bq*Sq)        // 16384
#define BHn   (Bq*Hq)        // 128
#define OUT_MAIN (Mrows*Dq)  // 16777216 floats of `outputs`

__device__ float g_Tq[Mrows*32];
__device__ float g_Tk[Mrows*32];
__device__ float g_Q [Mrows*Dq];
__device__ float g_K [Mrows*Dq];
__device__ float g_V [Mrows*Dq];
__device__ float g_VV[BHn*DHq*DHq];
__device__ float g_VVV[Mrows*Dq];
__device__ float g_O1[Mrows*Dq];
__device__ float g_O2[Mrows*Dq];

// fp16 buffers for tensor-core GEMMs (single-pass fp16, fp32 accumulate)
__device__ __align__(128) __half g_Ah[Mrows*Dq];
__device__ __align__(128) __half g_Bh[Dq*Dq];   // transposed weight [n][k]

// ===========================================================================
// PTX helpers (sm_80/90 baseline — compile under compute_103)
// ===========================================================================
__device__ __forceinline__ uint32_t smem_u32(const void* p) {
    uint32_t a;
    asm("{ .reg .u64 t; cvta.to.shared.u64 t, %1; cvt.u32.u64 %0, t; }" : "=r"(a) : "l"(p));
    return a;
}
__device__ __forceinline__ void cpa16(uint32_t s, const void* g) {
    asm volatile("cp.async.cg.shared.global [%0], [%1], 16;" :: "r"(s), "l"(g));
}
__device__ __forceinline__ void cpa_commit() {
    asm volatile("cp.async.commit_group;" ::: "memory");
}
__device__ __forceinline__ void cpa_wait1() {
    asm volatile("cp.async.wait_group 1;" ::: "memory");
}
__device__ __forceinline__ void ldsm4(uint32_t* r, uint32_t addr) {
    asm volatile("ldmatrix.sync.aligned.m8n8.x4.shared.b16 {%0,%1,%2,%3}, [%4];"
                 : "=r"(r[0]), "=r"(r[1]), "=r"(r[2]), "=r"(r[3]) : "r"(addr));
}
__device__ __forceinline__ void mma16816(float* c, const uint32_t* a, const uint32_t* b) {
    asm volatile(
        "mma.sync.aligned.m16n8k16.row.col.f32.f16.f16.f32 "
        "{%0,%1,%2,%3}, {%4,%5,%6,%7}, {%8,%9}, {%0,%1,%2,%3};"
        : "+f"(c[0]), "+f"(c[1]), "+f"(c[2]), "+f"(c[3])
        : "r"(a[0]), "r"(a[1]), "r"(a[2]), "r"(a[3]), "r"(b[0]), "r"(b[1]));
}

// ===========================================================================
// HMMA GEMM: C[16384,1024] = A @ W  (fp16 x1), 512 threads, 16 warps of 32x32.
// K-chunk 64, 2-stage cp.async pipeline.
// ===========================================================================
#define GP 72                      // smem row pitch in fp16 elems (64 + 8 pad)
#define ST_AH 0
#define ST_BH 18432                // 128*72*2
#define ST_BYTES 36864
#define HG_SMEM (2*ST_BYTES)

__device__ __forceinline__ void hg_load_stage(uint32_t sb, int st,
                                              int m0, int n0, int kc, int tid) {
    uint32_t base = sb + st * ST_BYTES;
    #pragma unroll
    for (int i = 0; i < 2; i++) {
        int idx = tid + i * 512;          // 0..1023 (128 rows x 8 16B-chunks)
        int row = idx >> 3, c8 = idx & 7;
        uint32_t so = (uint32_t)(row * GP + c8 * 8) * 2;
        cpa16(base + ST_AH + so, g_Ah + (size_t)(m0 + row) * Dq + kc + c8 * 8);
        cpa16(base + ST_BH + so, g_Bh + (size_t)(n0 + row) * Dq + kc + c8 * 8);
    }
}

__global__ void __launch_bounds__(512) k_hgemm(float* __restrict__ C) {
    extern __shared__ char smem[];
    uint32_t sb = smem_u32(smem);
    int tid = threadIdx.x;
    int lane = tid & 31, w = tid >> 5;
    int wm = w & 3, wn = w >> 2;          // warp tile: rows wm*32, cols wn*32
    int m0 = blockIdx.y * 128;
    int n0 = blockIdx.x * 128;

    float acc[2][4][4];
    #pragma unroll
    for (int i = 0; i < 2; i++)
        #pragma unroll
        for (int j = 0; j < 4; j++)
            #pragma unroll
            for (int k = 0; k < 4; k++) acc[i][j][k] = 0.f;

    hg_load_stage(sb, 0, m0, n0, 0, tid);
    cpa_commit();
    hg_load_stage(sb, 1, m0, n0, 64, tid);
    cpa_commit();
    cpa_wait1();
    __syncthreads();

    int aRow = lane & 15, aKo = (lane >> 4) << 3;
    int bRow = (lane & 7) + ((lane >> 4) << 3);
    int bKo = ((lane >> 3) & 1) << 3;

    for (int c = 0; c < 16; c++) {
        int st = c & 1;
        uint32_t s0 = sb + st * ST_BYTES;
        #pragma unroll
        for (int kh = 0; kh < 4; kh++) {
            uint32_t ah[2][4], bh[4][2];
            #pragma unroll
            for (int mt = 0; mt < 2; mt++) {
                uint32_t off = (uint32_t)((wm * 32 + mt * 16 + aRow) * GP + kh * 16 + aKo) * 2;
                ldsm4(ah[mt], s0 + ST_AH + off);
            }
            #pragma unroll
            for (int nt2 = 0; nt2 < 2; nt2++) {
                uint32_t off = (uint32_t)((wn * 32 + nt2 * 16 + bRow) * GP + kh * 16 + bKo) * 2;
                uint32_t r[4];
                ldsm4(r, s0 + ST_BH + off);
                bh[nt2*2][0] = r[0]; bh[nt2*2][1] = r[1];
                bh[nt2*2+1][0] = r[2]; bh[nt2*2+1][1] = r[3];
            }
            #pragma unroll
            for (int mt = 0; mt < 2; mt++)
                #pragma unroll
                for (int nt = 0; nt < 4; nt++) mma16816(acc[mt][nt], ah[mt], bh[nt]);
        }
        __syncthreads();
        if (c + 2 < 16)
            hg_load_stage(sb, st, m0, n0, (c + 2) * 64, tid);
        cpa_commit();
        cpa_wait1();
        __syncthreads();
    }

    #pragma unroll
    for (int mt = 0; mt < 2; mt++) {
        int r0 = m0 + wm * 32 + mt * 16 + (lane >> 2);
        #pragma unroll
        for (int nt = 0; nt < 4; nt++) {
            int col = n0 + wn * 32 + nt * 8 + (lane & 3) * 2;
            *(float2*)(C + (size_t)r0 * Dq + col)       = make_float2(acc[mt][nt][0], acc[mt][nt][1]);
            *(float2*)(C + (size_t)(r0 + 8) * Dq + col) = make_float2(acc[mt][nt][2], acc[mt][nt][3]);
        }
    }
}

// ===========================================================================
// fp32 -> fp16 convert into g_Ah (device global only — GB300 ATS trap!)
// ===========================================================================
__global__ void k_half(const float* __restrict__ x) {
    size_t i = ((size_t)blockIdx.x * 256 + threadIdx.x) * 4;
    float4 v = *(const float4*)(x + i);
    *(__half2*)(g_Ah + i)     = __floats2half2_rn(v.x, v.y);
    *(__half2*)(g_Ah + i + 2) = __floats2half2_rn(v.z, v.w);
}

// ===========================================================================
// fp32 W[k][n] -> transposed fp16 Wt[n][k]  (1024x1024)
// ===========================================================================
__global__ void k_halfT(const float* __restrict__ W) {
    __shared__ float t[32][33];
    int tx = threadIdx.x, ty = threadIdx.y;   // block (32,8)
    int bx = blockIdx.x, by = blockIdx.y;
    #pragma unroll
    for (int i = 0; i < 4; i++)
        t[ty + i*8][tx] = W[(size_t)(by*32 + ty + i*8) * Dq + bx*32 + tx];
    __syncthreads();
    #pragma unroll
    for (int i = 0; i < 4; i++) {
        size_t o = (size_t)(bx*32 + ty + i*8) * Dq + by*32 + tx;
        g_Bh[o] = __float2half(t[tx][ty + i*8]);
    }
}

// ---------------------------------------------------------------------------
// proj1: T = X @ W1   (X: [16384,1024], W1: [1024,32])
// block 256, tile 64 rows x 32 cols, k-chunk 64, 8 accumulators/thread.
// ---------------------------------------------------------------------------
__global__ void k_proj1(const float* __restrict__ X, const float* __restrict__ W, int sel) {
    __shared__ float Xs[64][64];
    __shared__ float Ws[64][32];
    float* T = sel ? g_Tk : g_Tq;
    int t = threadIdx.x;
    int row0 = blockIdx.x * 64;
    int tr = t >> 5, tc = t & 31;
    float acc[8];
    #pragma unroll
    for (int i = 0; i < 8; i++) acc[i] = 0.f;
    for (int kc = 0; kc < 1024; kc += 64) {
        #pragma unroll
        for (int i = 0; i < 4; i++) {
            int idx = t + i * 256;
            int r = idx >> 4, c = idx & 15;
            *(float4*)&Xs[r][c*4] = *(const float4*)(X + (size_t)(row0 + r) * 1024 + kc + c*4);
        }
        #pragma unroll
        for (int i = 0; i < 2; i++) {
            int idx = t + i * 256;
            int k = idx >> 3, c = idx & 7;
            *(float4*)&Ws[k][c*4] = *(const float4*)(W + (size_t)(kc + k) * 32 + c*4);
        }
        __syncthreads();
        #pragma unroll
        for (int k = 0; k < 64; k += 4) {
            float w0 = Ws[k][tc], w1 = Ws[k+1][tc], w2 = Ws[k+2][tc], w3 = Ws[k+3][tc];
            #pragma unroll
            for (int i = 0; i < 8; i++) {
                float4 x = *(const float4*)&Xs[tr*8 + i][k];
                acc[i] += x.x*w0 + x.y*w1 + x.z*w2 + x.w*w3;
            }
        }
        __syncthreads();
    }
    #pragma unroll
    for (int i = 0; i < 8; i++)
        T[(size_t)(row0 + tr*8 + i) * 32 + tc] = acc[i];
}

// ---------------------------------------------------------------------------
// proj2: O = T @ W2   (T: [16384,32], W2: [32,1024])
// block 256, tile 64 rows x 128 cols; W2 slice staged in smem once.
// ---------------------------------------------------------------------------
__global__ void k_proj2(const float* __restrict__ W2, int sel) {
    __shared__ float Ts[64][33];
    __shared__ float Ws[32][132];
    const float* T = sel ? g_Tk : g_Tq;
    float* O = sel ? g_K : g_Q;
    int t = threadIdx.x;
    int row0 = blockIdx.y * 64;
    int n0 = blockIdx.x * 128;
    #pragma unroll
    for (int i = 0; i < 2; i++) {
        int idx = (t + i * 256) * 4;          // 2048 floats of T
        int r = idx >> 5, k = idx & 31;
        float4 v = *(const float4*)(T + (size_t)(row0 + r) * 32 + k);
        Ts[r][k] = v.x; Ts[r][k+1] = v.y; Ts[r][k+2] = v.z; Ts[r][k+3] = v.w;
    }
    #pragma unroll
    for (int i = 0; i < 4; i++) {
        int idx = (t + i * 256) * 4;          // 4096 floats of W2 slice
        int k = idx >> 7, c = idx & 127;
        *(float4*)&Ws[k][c] = *(const float4*)(W2 + (size_t)k * 1024 + n0 + c);
    }
    __syncthreads();
    int tr = t >> 5, tc = t & 31;
    float acc[8][4];
    #pragma unroll
    for (int i = 0; i < 8; i++)
        #pragma unroll
        for (int j = 0; j < 4; j++) acc[i][j] = 0.f;
    #pragma unroll
    for (int k = 0; k < 32; k++) {
        float4 wv = *(const float4*)&Ws[k][tc*4];
        #pragma unroll
        for (int i = 0; i < 8; i++) {
            float tv = Ts[tr*8 + i][k];
            acc[i][0] += tv * wv.x;
            acc[i][1] += tv * wv.y;
            acc[i][2] += tv * wv.z;
            acc[i][3] += tv * wv.w;
        }
    }
    #pragma unroll
    for (int i = 0; i < 8; i++)
        *(float4*)(O + (size_t)(row0 + tr*8 + i) * 1024 + n0 + tc*4) =
            make_float4(acc[i][0], acc[i][1], acc[i][2], acc[i][3]);
}

// ---------------------------------------------------------------------------
// scores: attn[b,h,d,s] = scale * sum_f A[f,d] * K[b,h,s,f]   (raw scores)
// ---------------------------------------------------------------------------
__global__ void k_scores(const float* __restrict__ Amat, float* __restrict__ attn) {
    __shared__ float Asm[64][68];    // [d][f]  (A^T)
    __shared__ float Ksm[64][68];    // [sl][f]
    int bh = blockIdx.y;
    int b = bh >> 4, h = bh & 15;
    int s0 = blockIdx.x * 64;
    int t = threadIdx.x;
    for (int i = t; i < 4096; i += 256) {
        int f = i >> 6, d = i & 63;
        Asm[d][f] = Amat[i];
    }
    for (int i = t; i < 4096; i += 256) {
        int sl = i >> 6, f = i & 63;
        Ksm[sl][f] = g_K[(size_t)(b * Sq + s0 + sl) * 1024 + h * 64 + f];
    }
    __syncthreads();
    int sl = t & 63, dg = t >> 6;
    float acc[16];
    #pragma unroll
    for (int i = 0; i < 16; i++) acc[i] = 0.f;
    #pragma unroll
    for (int f4 = 0; f4 < 16; f4++) {
        float4 kv = *(const float4*)&Ksm[sl][f4*4];
        #pragma unroll
        for (int dd = 0; dd < 16; dd++) {
            float4 av = *(const float4*)&Asm[dg*16 + dd][f4*4];
            acc[dd] += kv.x*av.x + kv.y*av.y + kv.z*av.z + kv.w*av.w;
        }
    }
    #pragma unroll
    for (int dd = 0; dd < 16; dd++) {
        int d = dg * 16 + dd;
        attn[((size_t)(bh * 64 + d)) * Sq + s0 + sl] = acc[dd] * 0.125f;
    }
}

// ---------------------------------------------------------------------------
// softmax over s (row length 2048), in place.
// ---------------------------------------------------------------------------
__global__ void k_softmax(float* __restrict__ attn) {
    __shared__ float smx[8];
    __shared__ float sms[8];
    float* p = attn + (size_t)blockIdx.x * Sq;
    int t = threadIdx.x;
    float v[8];
    float m = -1e30f;
    #pragma unroll
    for (int i = 0; i < 8; i++) { v[i] = p[t + i * 256]; m = fmaxf(m, v[i]); }
    #pragma unroll
    for (int o = 16; o > 0; o >>= 1) m = fmaxf(m, __shfl_xor_sync(0xffffffffu, m, o));
    if ((t & 31) == 0) smx[t >> 5] = m;
    __syncthreads();
    m = smx[0];
    #pragma unroll
    for (int i = 1; i < 8; i++) m = fmaxf(m, smx[i]);
    float l = 0.f;
    #pragma unroll
    for (int i = 0; i < 8; i++) { v[i] = __expf(v[i] - m); l += v[i]; }
    #pragma unroll
    for (int o = 16; o > 0; o >>= 1) l += __shfl_xor_sync(0xffffffffu, l, o);
    if ((t & 31) == 0) sms[t >> 5] = l;
    __syncthreads();
    l = 0.f;
    #pragma unroll
    for (int i = 0; i < 8; i++) l += sms[i];
    float inv = 1.f / l;
    #pragma unroll
    for (int i = 0; i < 8; i++) p[t + i * 256] = v[i] * inv;
}

// ---------------------------------------------------------------------------
// VV[bh][d][f] += sum_{s in split} attn[bh,d,s] * V[b,s,h*64+f]
// ---------------------------------------------------------------------------
__global__ void k_vv(const float* __restrict__ attn) {
    __shared__ float At[64][65];
    __shared__ float Vs[64][65];
    int split = blockIdx.x;
    int bh = blockIdx.y;
    int b = bh >> 4, h = bh & 15;
    int t = threadIdx.x;
    int tr = t >> 4, tc = t & 15;
    float acc[4][4];
    #pragma unroll
    for (int i = 0; i < 4; i++)
        #pragma unroll
        for (int j = 0; j < 4; j++) acc[i][j] = 0.f;
    int sbeg = split * 512;
    for (int sc0 = sbeg; sc0 < sbeg + 512; sc0 += 64) {
        for (int i = t; i < 4096; i += 256) {
            int d = i >> 6, ss = i & 63;
            At[d][ss] = attn[((size_t)(bh * 64 + d)) * Sq + sc0 + ss];
        }
        for (int i = t; i < 4096; i += 256) {
            int ss = i >> 6, f = i & 63;
            Vs[ss][f] = g_V[(size_t)(b * Sq + sc0 + ss) * 1024 + h * 64 + f];
        }
        __syncthreads();
        #pragma unroll 8
        for (int ss = 0; ss < 64; ss++) {
            float av[4], bv[4];
            #pragma unroll
            for (int i = 0; i < 4; i++) av[i] = At[tr * 4 + i][ss];
            #pragma unroll
            for (int j = 0; j < 4; j++) bv[j] = Vs[ss][tc * 4 + j];
            #pragma unroll
            for (int i = 0; i < 4; i++)
                #pragma unroll
                for (int j = 0; j < 4; j++) acc[i][j] += av[i] * bv[j];
        }
        __syncthreads();
    }
    #pragma unroll
    for (int i = 0; i < 4; i++)
        #pragma unroll
        for (int j = 0; j < 4; j++)
            atomicAdd(&g_VV[(size_t)bh * 4096 + (tr * 4 + i) * 64 + tc * 4 + j], acc[i][j]);
}

// ---------------------------------------------------------------------------
// stage 2: two-pass softmax (scores in regs), float4 LDS, halves for output.
// ---------------------------------------------------------------------------
__global__ void k_stage2(const float* __restrict__ Amat) {
    __shared__ float Asm[64][68];   // A[d][f]
    __shared__ float VVs[64][68];   // VV[d][f]
    int bh = blockIdx.y;
    int b = bh >> 4, h = bh & 15;
    int s0 = blockIdx.x * 128;
    int t = threadIdx.x;
    for (int i = t; i < 4096; i += 128) {
        int d = i >> 6, f = i & 63;
        Asm[d][f] = Amat[i];
        VVs[d][f] = g_VV[(size_t)bh * 4096 + i];
    }
    __syncthreads();
    int s = s0 + t;
    const float* Qrow = g_Q + (size_t)(b * Sq + s) * 1024 + h * 64;
    float qr[64];
    #pragma unroll
    for (int f4 = 0; f4 < 64; f4 += 4) {
        float4 q = *(const float4*)(Qrow + f4);
        qr[f4] = q.x; qr[f4+1] = q.y; qr[f4+2] = q.z; qr[f4+3] = q.w;
    }
    float sc[64];
    #pragma unroll
    for (int d = 0; d < 64; d++) {
        float sum = 0.f;
        #pragma unroll
        for (int f4 = 0; f4 < 16; f4++) {
            float4 av = *(const float4*)&Asm[d][f4*4];
            sum += qr[f4*4]*av.x + qr[f4*4+1]*av.y + qr[f4*4+2]*av.z + qr[f4*4+3]*av.w;
        }
        sc[d] = sum * 0.125f;
    }
    float m = sc[0];
    #pragma unroll
    for (int d = 1; d < 64; d++) m = fmaxf(m, sc[d]);
    float l = 0.f;
    #pragma unroll
    for (int d = 0; d < 64; d++) { float e = __expf(sc[d] - m); sc[d] = e; l += e; }
    float inv = 1.f / l;
    float* Orow = g_VVV + ((size_t)bh * Sq + s) * 64;
    #pragma unroll
    for (int half = 0; half < 2; half++) {
        float out[32];
        #pragma unroll
        for (int j = 0; j < 32; j++) out[j] = 0.f;
        #pragma unroll 8
        for (int d = 0; d < 64; d++) {
            float p = sc[d];
            #pragma unroll
            for (int f4 = 0; f4 < 8; f4++) {
                float4 vv = *(const float4*)&VVs[d][half*32 + f4*4];
                out[f4*4]   += p * vv.x;
                out[f4*4+1] += p * vv.y;
                out[f4*4+2] += p * vv.z;
                out[f4*4+3] += p * vv.w;
            }
        }
        #pragma unroll
        for (int j = 0; j < 32; j += 4)
            *(float4*)(Orow + half*32 + j) = make_float4(out[j]*inv, out[j+1]*inv,
                                                         out[j+2]*inv, out[j+3]*inv);
    }
}

// ---------------------------------------------------------------------------
// LayerNorm over last dim (1024), x = in1 + res.
// sel=0: in1=g_VVV, res=Xq, out=g_O1, ALSO emits fp16 to g_Ah.
// sel=1: in1=g_O2,  res=g_O1, out=d_out.
// ---------------------------------------------------------------------------
__global__ void k_ln(const float* __restrict__ rese, const float* __restrict__ g,
                     const float* __restrict__ bb, float* __restrict__ oute, int sel) {
    const float* in1 = sel ? g_O2 : g_VVV;
    const float* res = sel ? g_O1 : rese;
    float* out = sel ? oute : g_O1;
    __shared__ float sm1[8];
    __shared__ float sm2[8];
    size_t base = (size_t)blockIdx.x * 1024;
    int t = threadIdx.x;
    float v[4];
    float sum = 0.f;
    #pragma unroll
    for (int i = 0; i < 4; i++) {
        int c = t + i * 256;
        v[i] = in1[base + c] + res[base + c];
        sum += v[i];
    }
    #pragma unroll
    for (int o = 16; o > 0; o >>= 1) sum += __shfl_xor_sync(0xffffffffu, sum, o);
    if ((t & 31) == 0) sm1[t >> 5] = sum;
    __syncthreads();
    sum = 0.f;
    #pragma unroll
    for (int i = 0; i < 8; i++) sum += sm1[i];
    float mean = sum * (1.f / 1024.f);
    float sq = 0.f;
    #pragma unroll
    for (int i = 0; i < 4; i++) { float d = v[i] - mean; sq += d * d; }
    #pragma unroll
    for (int o = 16; o > 0; o >>= 1) sq += __shfl_xor_sync(0xffffffffu, sq, o);
    if ((t & 31) == 0) sm2[t >> 5] = sq;
    __syncthreads();
    sq = 0.f;
    #pragma unroll
    for (int i = 0; i < 8; i++) sq += sm2[i];
    float rstd = rsqrtf(sq * (1.f / 1024.f) + 1e-5f);
    #pragma unroll
    for (int i = 0; i < 4; i++) {
        int c = t + i * 256;
        float o = (v[i] - mean) * rstd * g[c] + bb[c];
        out[base + c] = o;
        if (sel == 0) g_Ah[base + c] = __float2half(o);
    }
}

// ===========================================================================
// Host side
// ===========================================================================
extern "C" void kernel_launch(void* const* d_in, const int* in_sizes, int n_in,
                              void* d_out, int out_size) {
    const float* Xq  = (const float*)d_in[0];
    const float* Xk  = (const float*)d_in[1];
    const float* Xv  = (const float*)d_in[2];
    const float* Wq1 = (const float*)d_in[3];
    const float* Wq2 = (const float*)d_in[4];
    const float* Wk1 = (const float*)d_in[5];
    const float* Wk2 = (const float*)d_in[6];
    const float* Wv  = (const float*)d_in[7];
    const float* Wfc = (const float*)d_in[8];
    const float* Am  = (const float*)d_in[9];
    const float* lng = (const float*)d_in[10];
    const float* lnb = (const float*)d_in[11];
    float* out = (float*)d_out;
    size_t attn_off = (out_size > OUT_MAIN) ? (size_t)(out_size - OUT_MAIN) : 0;
    float* attn = out + attn_off;

    void *pV, *pO2, *pVV;
    cudaGetSymbolAddress(&pV,  g_V);
    cudaGetSymbolAddress(&pO2, g_O2);
    cudaGetSymbolAddress(&pVV, g_VV);

    cudaFuncSetAttribute(k_hgemm, cudaFuncAttributeMaxDynamicSharedMemorySize, HG_SMEM);

    k_proj1<<<256, 256>>>(Xq, Wq1, 0);
    k_proj1<<<256, 256>>>(Xk, Wk1, 1);
    k_proj2<<<dim3(8, 256), 256>>>(Wq2, 0);
    k_proj2<<<dim3(8, 256), 256>>>(Wk2, 1);

    // V = Xv @ Wv on tensor cores (fp16 x1, mma.sync)
    k_half<<<16384, 256>>>(Xv);
    k_halfT<<<dim3(32, 32), dim3(32, 8)>>>(Wv);
    k_hgemm<<<dim3(8, 128), 512, HG_SMEM>>>((float*)pV);

    k_scores<<<dim3(32, 128), 256>>>(Am, attn);
    k_softmax<<<8192, 256>>>(attn);
    cudaMemsetAsync(pVV, 0, (size_t)BHn * DHq * DHq * sizeof(float));
    k_vv<<<dim3(4, 128), 256>>>(attn);
    k_stage2<<<dim3(16, 128), 128>>>(Am);
    k_ln<<<16384, 256>>>(Xq, lng, lnb, nullptr, 0);      // out1 = LN(VVV+Xq) + fp16

    // out2 = out1 @ Wfc on tensor cores (fp16 x1, mma.sync)
    k_halfT<<<dim3(32, 32), dim3(32, 8)>>>(Wfc);
    k_hgemm<<<dim3(8, 128), 512, HG_SMEM>>>((float*)pO2);

    k_ln<<<16384, 256>>>(nullptr, lng, lnb, out, 1);     // out = LN(out2 + out1)
}